// round 13
// baseline (speedup 1.0000x reference)
#include <cuda_runtime.h>
#include <cuda_fp16.h>
#include <cuda_bf16.h>
#include <cstdint>

// ===================== problem constants =====================
#define M_TOTAL 16384
#define N_TOTAL 12288
#define K_TOTAL 4096
#define THREADS 256

// runtime-detected input/output dtype: 0 = fp16, 1 = bf16, 2 = fp32
__device__ int g_dtype;

// fp16 staging buffers (device globals: allowed scratch)
static __device__ __align__(16) __half g_x[(size_t)M_TOTAL * K_TOTAL];     // 134 MB
static __device__ __align__(16) __half g_w[(size_t)N_TOTAL * K_TOTAL];     // 100 MB
static __device__ __align__(16) __half g_bias[N_TOTAL];

// ===================== PTX helpers (sm_80/90 baseline only) =====================
__device__ __forceinline__ uint32_t smem_u32(const void* p) {
    uint32_t a;
    asm("{ .reg .u64 t; cvta.to.shared.u64 t, %1; cvt.u32.u64 %0, t; }" : "=r"(a) : "l"(p));
    return a;
}
#define CP16(dst, src) asm volatile("cp.async.cg.shared.global [%0], [%1], 16;" :: "r"(dst), "l"(src) : "memory")
#define CP_COMMIT()    asm volatile("cp.async.commit_group;" ::: "memory")

#define LDSM4(r0, r1, r2, r3, addr) \
    asm volatile("ldmatrix.sync.aligned.m8n8.x4.shared.b16 {%0,%1,%2,%3}, [%4];" \
        : "=r"(r0), "=r"(r1), "=r"(r2), "=r"(r3) : "r"(addr))

#define MMA16816(c, a, b0, b1) \
    asm volatile("mma.sync.aligned.m16n8k16.row.col.f32.f16.f16.f32 " \
        "{%0,%1,%2,%3}, {%4,%5,%6,%7}, {%8,%9}, {%0,%1,%2,%3};" \
        : "+f"((c)[0]), "+f"((c)[1]), "+f"((c)[2]), "+f"((c)[3]) \
        : "r"((a)[0]), "r"((a)[1]), "r"((a)[2]), "r"((a)[3]), "r"(b0), "r"(b1))

__device__ __forceinline__ __half load_h(const void* p, int i, int dt) {
    if (dt == 2) return __float2half(((const float*)p)[i]);
    if (dt == 1) return __float2half(__bfloat162float(((const __nv_bfloat16*)p)[i]));
    return ((const __half*)p)[i];
}

// ===================== launch 0: sniff dtype + convert bias (1 block) =====================
// Words of x as fp32: plausible |v| => fp32 or bf16 (high half valid value);
// low 13 mantissa bits zero => fp16-upcast-to-fp32 signature. Packed fp16 fails both.
__global__ void sniff_bias_kernel(const uint32_t* __restrict__ xw,
                                  const void* __restrict__ bias) {
    __shared__ int sA, sB, sDT;
    if (threadIdx.x == 0) { sA = 0; sB = 0; }
    __syncthreads();
    int a = 0, b = 0;
    for (int i = threadIdx.x; i < 1024; i += THREADS) {
        uint32_t w = xw[i];
        float af = fabsf(__uint_as_float(w));
        if (af >= 9.5367431640625e-7f && af <= 16.0f) a++;   // [2^-20, 2^4]
        if ((w & 0x1FFFu) == 0) b++;
    }
    atomicAdd(&sA, a);
    atomicAdd(&sB, b);
    __syncthreads();
    if (threadIdx.x == 0) {
        int dt = (sA > 512) ? ((sB > 512) ? 2 : 1) : 0;
        g_dtype = dt;
        sDT = dt;
    }
    __syncthreads();
    int dt = sDT;
    for (int i = threadIdx.x; i < N_TOTAL; i += THREADS)
        g_bias[i] = load_h(bias, i, dt);
}

// ===================== launch 1: fused x-convert + weight-dequant =====================
#define XBLOCKS ((M_TOTAL * K_TOTAL / 8) / THREADS)    // 32768
#define WBLOCKS ((N_TOTAL * (K_TOTAL / 2) / 4) / THREADS)  // 24576

__global__ void __launch_bounds__(THREADS)
fused_convert_kernel(const void* __restrict__ x, const int* __restrict__ q,
                     const void* __restrict__ norm) {
    int dt = g_dtype;
    if (blockIdx.x < XBLOCKS) {
        // ---- x -> fp16 g_x, 8 elements per thread ----
        int i = blockIdx.x * THREADS + threadIdx.x;
        uint4 o;
        if (dt == 2) {
            const float4* p = (const float4*)x;
            float4 f0 = p[2 * i], f1 = p[2 * i + 1];
            __half2 h0 = __floats2half2_rn(f0.x, f0.y);
            __half2 h1 = __floats2half2_rn(f0.z, f0.w);
            __half2 h2 = __floats2half2_rn(f1.x, f1.y);
            __half2 h3 = __floats2half2_rn(f1.z, f1.w);
            o = make_uint4(*(uint32_t*)&h0, *(uint32_t*)&h1, *(uint32_t*)&h2, *(uint32_t*)&h3);
        } else if (dt == 1) {
            uint4 v = ((const uint4*)x)[i];
            uint32_t w[4] = {v.x, v.y, v.z, v.w}, r[4];
#pragma unroll
            for (int t = 0; t < 4; t++) {
                __nv_bfloat162 b2 = *reinterpret_cast<__nv_bfloat162*>(&w[t]);
                float2 f = __bfloat1622float2(b2);
                __half2 h = __floats2half2_rn(f.x, f.y);
                r[t] = *(uint32_t*)&h;
            }
            o = make_uint4(r[0], r[1], r[2], r[3]);
        } else {
            o = ((const uint4*)x)[i];
        }
        ((uint4*)g_x)[i] = o;
    } else {
        // ---- weight dequant: one int4 (4 packed bytes -> 8 fp16) per thread ----
        // w[2k] = fp16(lo)/fp16(15)*(fp16(2)*norm) - norm ; w[2k+1] with hi nibble.
        int idx = (blockIdx.x - XBLOCKS) * THREADS + threadIdx.x;
        int4 v = reinterpret_cast<const int4*>(q)[idx];
        int row = idx >> 9;                            // 512 int4 per 2048-int32 row
        __half n  = load_h(norm, row, dt);
        __half n2 = __hmul(n, __float2half(2.0f));
        const __half f15 = __float2half(15.0f);
        int bv[4] = {v.x, v.y, v.z, v.w};
        uint32_t o[4];
#pragma unroll
        for (int t = 0; t < 4; t++) {
            int b = bv[t];
            __half lo = __float2half((float)(b & 15));
            __half hi = __float2half((float)((b >> 4) & 15));
            __half wl = __hsub(__hmul(__hdiv(lo, f15), n2), n);
            __half wh = __hsub(__hmul(__hdiv(hi, f15), n2), n);
            __half2 h2 = __halves2half2(wl, wh);
            o[t] = *reinterpret_cast<uint32_t*>(&h2);
        }
        reinterpret_cast<uint4*>(g_w)[idx] = make_uint4(o[0], o[1], o[2], o[3]);
    }
}

// ===================== launch 2: GEMM =====================
// D[m][n] = sum_k g_x[m][k] * g_w[n][k] + bias[n]
// 8 warps as 2M x 4N, warp tile 64x64, m16n8k16 HMMA, 4-stage cp.async pipeline.
template<int BN_, int BK_>
__device__ __forceinline__ void load_chunk(const __half* __restrict__ aG,
                                           const __half* __restrict__ bG,
                                           int chunk, uint32_t base) {
    constexpr uint32_t ROWB_ = 2 * BK_ + 16;
    constexpr int S = BK_ / 8;                     // 16B segs per row
    constexpr uint32_t ASTG_ = 128 * ROWB_;
    int tid = threadIdx.x;
#pragma unroll
    for (int i = 0; i < 128 * S / THREADS; i++) {  // A: 128 rows
        int idx = tid + i * THREADS;
        int row = idx / S, seg = idx % S;
        CP16(base + (uint32_t)row * ROWB_ + (uint32_t)seg * 16,
             aG + (size_t)row * K_TOTAL + chunk * BK_ + seg * 8);
    }
#pragma unroll
    for (int i = 0; i < BN_ * S / THREADS; i++) {  // B: BN_ rows
        int idx = tid + i * THREADS;
        int row = idx / S, seg = idx % S;
        CP16(base + ASTG_ + (uint32_t)row * ROWB_ + (uint32_t)seg * 16,
             bG + (size_t)row * K_TOTAL + chunk * BK_ + seg * 8);
    }
}

template<int BN_, int BK_, int STAGES_>
__global__ void __launch_bounds__(THREADS, 1)
l4b_gemm_kernel(void* __restrict__ out) {
    constexpr int BM = 128;
    constexpr int NCH = K_TOTAL / BK_;
    constexpr uint32_t ROWB_ = 2 * BK_ + 16;
    constexpr uint32_t ASTG_ = 128 * ROWB_;
    constexpr uint32_t STG_  = ASTG_ + BN_ * ROWB_;
    constexpr int NSLAB = BN_ / 64;                // n16 slabs per warp (WN=4)
    extern __shared__ char smem[];
    const uint32_t sb = smem_u32(smem);
    const int tid  = threadIdx.x;
    const int wid  = tid >> 5;
    const int lane = tid & 31;
    const int dt = g_dtype;

    // rasterization: groups of 16 m-tiles for B-tile L2 reuse
    const int NT = N_TOTAL / BN_;
    const int GM = 16;
    int pid = blockIdx.x;
    int per_group = GM * NT;
    int grp = pid / per_group;
    int r = pid - grp * per_group;
    int m_tile = grp * GM + (r % GM);
    int n_tile = r / GM;

    const __half* aG = g_x + (size_t)m_tile * BM * K_TOTAL;
    const __half* bG = g_w + (size_t)n_tile * BN_ * K_TOTAL;

    const int warp_m = wid >> 2;   // 0..1 -> 64-row M slice
    const int warp_n = wid & 3;    // 0..3 -> BN_/4-col N slice

    float c[4][NSLAB * 2][4] = {};

    // prologue: stages 0..STAGES-2
#pragma unroll
    for (int s = 0; s < STAGES_ - 1; s++) {
        load_chunk<BN_, BK_>(aG, bG, s, sb + (uint32_t)s * STG_);
        CP_COMMIT();
    }

    for (int i = 0; i < NCH; i++) {
        asm volatile("cp.async.wait_group %0;" :: "n"(STAGES_ - 2) : "memory");
        __syncthreads();

        // issue next chunk's loads FIRST (slot (i-1)%S was retired by the sync above)
        int j = i + STAGES_ - 1;
        if (j < NCH)
            load_chunk<BN_, BK_>(aG, bG, j, sb + (uint32_t)(j % STAGES_) * STG_);
        CP_COMMIT();   // empty group in the tail is legal and completes immediately

        uint32_t aBase = sb + (uint32_t)(i % STAGES_) * STG_;
        uint32_t bBase = aBase + ASTG_;

#pragma unroll
        for (int ks = 0; ks < BK_ / 16; ks++) {
            uint32_t a[4][4];
#pragma unroll
            for (int mi = 0; mi < 4; mi++) {       // canonical x4 A: 64 rows
                int row = warp_m * 64 + mi * 16 + (lane & 15);
                uint32_t addr = aBase + (uint32_t)row * ROWB_
                              + (uint32_t)(ks * 32 + (lane >> 4) * 16);
                LDSM4(a[mi][0], a[mi][1], a[mi][2], a[mi][3], addr);
            }
#pragma unroll
            for (int np = 0; np < NSLAB; np++) {   // canonical x4 B: BN_/4 cols
                uint32_t b0, b1, b2, b3;           // r0=(n0-7,k0-7) r1=(n8-15,k0-7)
                int nrow = warp_n * (BN_ / 4) + np * 16 + (lane & 15);
                uint32_t addr = bBase + (uint32_t)nrow * ROWB_
                              + (uint32_t)(ks * 32 + (lane >> 4) * 16);
                LDSM4(b0, b1, b2, b3, addr);       // r2=(n0-7,k8-15) r3=(n8-15,k8-15)
#pragma unroll
                for (int mi = 0; mi < 4; mi++) {
                    MMA16816(c[mi][np * 2],     a[mi], b0, b2);
                    MMA16816(c[mi][np * 2 + 1], a[mi], b1, b3);
                }
            }
        }
    }

    // epilogue: fp16(acc) + bias in fp16 (matches reference), store per dtype
    {
        int m0 = m_tile * BM + warp_m * 64;
        int n0 = n_tile * BN_ + warp_n * (BN_ / 4);
        int mrow = lane >> 2;
        int ncol = (lane & 3) * 2;
#pragma unroll
        for (int mi = 0; mi < 4; mi++) {
            int m = m0 + mi * 16 + mrow;
            size_t orow0 = (size_t)m * N_TOTAL;
            size_t orow1 = (size_t)(m + 8) * N_TOTAL;
#pragma unroll
            for (int ni = 0; ni < NSLAB * 2; ni++) {
                int n = n0 + ni * 8 + ncol;
                __half2 bb = *reinterpret_cast<const __half2*>(g_bias + n);
                __half2 v0 = __hadd2(__floats2half2_rn(c[mi][ni][0], c[mi][ni][1]), bb);
                __half2 v1 = __hadd2(__floats2half2_rn(c[mi][ni][2], c[mi][ni][3]), bb);
                if (dt == 2) {
                    *reinterpret_cast<float2*>((float*)out + orow0 + n) = __half22float2(v0);
                    *reinterpret_cast<float2*>((float*)out + orow1 + n) = __half22float2(v1);
                } else if (dt == 1) {
                    float2 f0 = __half22float2(v0), f1 = __half22float2(v1);
                    __nv_bfloat162 z0 = __floats2bfloat162_rn(f0.x, f0.y);
                    __nv_bfloat162 z1 = __floats2bfloat162_rn(f1.x, f1.y);
                    *reinterpret_cast<__nv_bfloat162*>((__nv_bfloat16*)out + orow0 + n) = z0;
                    *reinterpret_cast<__nv_bfloat162*>((__nv_bfloat16*)out + orow1 + n) = z1;
                } else {
                    *reinterpret_cast<__half2*>((__half*)out + orow0 + n) = v0;
                    *reinterpret_cast<__half2*>((__half*)out + orow1 + n) = v1;
                }
            }
        }
    }
}

// ===================== launch =====================
extern "C" void kernel_launch(void* const* d_in, const int* in_sizes, int n_in,
                              void* d_out, int out_size) {
    // identify inputs by unique element counts (order-scheme independent)
    const void* x = nullptr; const int* wq = nullptr;
    const void* wnorm = nullptr; const void* bias = nullptr;
    int x_idx = -1;
    for (int i = 0; i < n_in; i++) {
        if (in_sizes[i] == 67108864) { x = d_in[i]; x_idx = i; }
        else if (in_sizes[i] == 25165824) { wq = (const int*)d_in[i]; }
    }
    {
        const void* small[2] = {nullptr, nullptr};
        int ns = 0;
        for (int i = 0; i < n_in; i++)
            if (in_sizes[i] == 12288 && ns < 2) small[ns++] = d_in[i];
        if (x_idx == 0) { wnorm = small[0]; bias = small[1]; }   // dict order
        else           { bias  = small[0]; wnorm = small[1]; }   // alphabetical
    }

    sniff_bias_kernel<<<1, THREADS>>>((const uint32_t*)x, bias);
    fused_convert_kernel<<<XBLOCKS + WBLOCKS, THREADS>>>(x, wq, wnorm);

    // main config: BN=256, BK=64, 4 stages -> 221184 B dynamic smem
    constexpr int MAIN_SMEM = 4 * (128 * 144 + 256 * 144);
    cudaError_t e = cudaFuncSetAttribute(l4b_gemm_kernel<256, 64, 4>,
                                         cudaFuncAttributeMaxDynamicSharedMemorySize,
                                         MAIN_SMEM);
    if (e == cudaSuccess) {
        l4b_gemm_kernel<256, 64, 4><<<(M_TOTAL / 128) * (N_TOTAL / 256), THREADS,
                                      MAIN_SMEM>>>(d_out);
    } else {
        // fallback: BN=128, BK=32, 2 stages -> 40960 B (< 48KB default limit)
        constexpr int FB_SMEM = 2 * (128 * 80 + 128 * 80);
        l4b_gemm_kernel<128, 32, 2><<<(M_TOTAL / 128) * (N_TOTAL / 128), THREADS,
                                      FB_SMEM>>>(d_out);
    }
}

// round 16
// speedup vs baseline: 1.0572x; 1.0572x over previous
#include <cuda_runtime.h>
#include <cuda_fp16.h>
#include <cuda_bf16.h>
#include <cstdint>

// ===================== problem constants =====================
#define M_TOTAL 16384
#define N_TOTAL 12288
#define K_TOTAL 4096
#define THREADS 256

// fp16 staging buffers (device globals: allowed scratch)
static __device__ __align__(16) __half g_x[(size_t)M_TOTAL * K_TOTAL];     // 134 MB
static __device__ __align__(16) __half g_w[(size_t)N_TOTAL * K_TOTAL];     // 100 MB
static __device__ __align__(16) __half g_bias[N_TOTAL];

// ===================== PTX helpers (sm_80/90 baseline only) =====================
__device__ __forceinline__ uint32_t smem_u32(const void* p) {
    uint32_t a;
    asm("{ .reg .u64 t; cvta.to.shared.u64 t, %1; cvt.u32.u64 %0, t; }" : "=r"(a) : "l"(p));
    return a;
}
#define CP16(dst, src) asm volatile("cp.async.cg.shared.global [%0], [%1], 16;" :: "r"(dst), "l"(src) : "memory")
#define CP_COMMIT()    asm volatile("cp.async.commit_group;" ::: "memory")

#define LDSM4(r0, r1, r2, r3, addr) \
    asm volatile("ldmatrix.sync.aligned.m8n8.x4.shared.b16 {%0,%1,%2,%3}, [%4];" \
        : "=r"(r0), "=r"(r1), "=r"(r2), "=r"(r3) : "r"(addr))

#define MMA16816(c, a, b0, b1) \
    asm volatile("mma.sync.aligned.m16n8k16.row.col.f32.f16.f16.f32 " \
        "{%0,%1,%2,%3}, {%4,%5,%6,%7}, {%8,%9}, {%0,%1,%2,%3};" \
        : "+f"((c)[0]), "+f"((c)[1]), "+f"((c)[2]), "+f"((c)[3]) \
        : "r"((a)[0]), "r"((a)[1]), "r"((a)[2]), "r"((a)[3]), "r"(b0), "r"(b1))

__device__ __forceinline__ __half load_h(const void* p, int i, int dt) {
    if (dt == 2) return __float2half(((const float*)p)[i]);
    if (dt == 1) return __float2half(__bfloat162float(((const __nv_bfloat16*)p)[i]));
    return ((const __half*)p)[i];
}

// ===================== inline dtype detection (per block, no extra launch) ==========
// Words of x as fp32: plausible |v| => fp32 or bf16 (high half is a valid value);
// low 13 mantissa bits all zero => fp16-upcast-to-fp32 signature.
// Packed-fp16 words decode to tiny fp32 exponents and fail the magnitude test.
// Requires all THREADS threads to participate (uses __syncthreads_count).
__device__ __forceinline__ int detect_dtype(const uint32_t* __restrict__ xw) {
    int t = threadIdx.x;
    int condA = 0, condB = 0;
    if (t < 256) {
        uint32_t w = xw[t];
        float af = fabsf(__uint_as_float(w));
        condA = (af >= 9.5367431640625e-7f && af <= 16.0f);   // [2^-20, 2^4]
        condB = ((w & 0x1FFFu) == 0);
    }
    int a = __syncthreads_count(condA);
    int b = __syncthreads_count(condB);
    return (a > 128) ? ((b > 128) ? 2 : 1) : 0;
}

// ===================== launch 0: fused x-convert + weight-dequant + bias ============
#define XBLOCKS ((M_TOTAL * K_TOTAL / 8) / THREADS)          // 32768
#define WBLOCKS ((N_TOTAL * (K_TOTAL / 2) / 4) / THREADS)    // 24576
#define BBLOCKS (N_TOTAL / THREADS)                          // 48

__global__ void __launch_bounds__(THREADS)
fused_convert_kernel(const void* __restrict__ x, const int* __restrict__ q,
                     const void* __restrict__ norm, const void* __restrict__ bias) {
    int dt = detect_dtype((const uint32_t*)x);
    if (blockIdx.x < XBLOCKS) {
        // ---- x -> fp16 g_x, 8 elements per thread ----
        int i = blockIdx.x * THREADS + threadIdx.x;
        uint4 o;
        if (dt == 2) {
            const float4* p = (const float4*)x;
            float4 f0 = p[2 * i], f1 = p[2 * i + 1];
            __half2 h0 = __floats2half2_rn(f0.x, f0.y);
            __half2 h1 = __floats2half2_rn(f0.z, f0.w);
            __half2 h2 = __floats2half2_rn(f1.x, f1.y);
            __half2 h3 = __floats2half2_rn(f1.z, f1.w);
            o = make_uint4(*(uint32_t*)&h0, *(uint32_t*)&h1, *(uint32_t*)&h2, *(uint32_t*)&h3);
        } else if (dt == 1) {
            uint4 v = ((const uint4*)x)[i];
            uint32_t w[4] = {v.x, v.y, v.z, v.w}, r[4];
#pragma unroll
            for (int t = 0; t < 4; t++) {
                __nv_bfloat162 b2 = *reinterpret_cast<__nv_bfloat162*>(&w[t]);
                float2 f = __bfloat1622float2(b2);
                __half2 h = __floats2half2_rn(f.x, f.y);
                r[t] = *(uint32_t*)&h;
            }
            o = make_uint4(r[0], r[1], r[2], r[3]);
        } else {
            o = ((const uint4*)x)[i];
        }
        ((uint4*)g_x)[i] = o;
    } else if (blockIdx.x < XBLOCKS + WBLOCKS) {
        // ---- weight dequant: one int4 (4 packed bytes -> 8 fp16) per thread ----
        // w[2k] = fp16(lo)/fp16(15)*(fp16(2)*norm) - norm ; w[2k+1] with hi nibble.
        // Exact fp16-arithmetic emulation of the reference.
        int idx = (blockIdx.x - XBLOCKS) * THREADS + threadIdx.x;
        int4 v = reinterpret_cast<const int4*>(q)[idx];
        int row = idx >> 9;                            // 512 int4 per 2048-int32 row
        __half n  = load_h(norm, row, dt);
        __half n2 = __hmul(n, __float2half(2.0f));
        const __half f15 = __float2half(15.0f);
        int bv[4] = {v.x, v.y, v.z, v.w};
        uint32_t o[4];
#pragma unroll
        for (int t = 0; t < 4; t++) {
            int b = bv[t];
            __half lo = __float2half((float)(b & 15));
            __half hi = __float2half((float)((b >> 4) & 15));
            __half wl = __hsub(__hmul(__hdiv(lo, f15), n2), n);
            __half wh = __hsub(__hmul(__hdiv(hi, f15), n2), n);
            __half2 h2 = __halves2half2(wl, wh);
            o[t] = *reinterpret_cast<uint32_t*>(&h2);
        }
        reinterpret_cast<uint4*>(g_w)[idx] = make_uint4(o[0], o[1], o[2], o[3]);
    } else {
        // ---- bias -> fp16 ----
        int i = (blockIdx.x - XBLOCKS - WBLOCKS) * THREADS + threadIdx.x;
        g_bias[i] = load_h(bias, i, dt);
    }
}

// ===================== launch 1: GEMM =====================
// D[m][n] = sum_k g_x[m][k] * g_w[n][k] + bias[n]
// R9 structure: CTA 128x256, 8 warps (4M x 2N), warp tile 32x128,
// m16n8k16 HMMA, 3-stage cp.async, MMA-then-load order.
// New: B-fragment register prefetch (np+1 LDSM issued before np's MMAs).
template<int BN_, int BK_>
__device__ __forceinline__ void load_chunk(const __half* __restrict__ aG,
                                           const __half* __restrict__ bG,
                                           int chunk, uint32_t base) {
    constexpr uint32_t ROWB_ = 2 * BK_ + 16;
    constexpr int S = BK_ / 8;                     // 16B segs per row
    constexpr uint32_t ASTG_ = 128 * ROWB_;
    int tid = threadIdx.x;
#pragma unroll
    for (int i = 0; i < 128 * S / THREADS; i++) {  // A: 128 rows
        int idx = tid + i * THREADS;
        int row = idx / S, seg = idx % S;
        CP16(base + (uint32_t)row * ROWB_ + (uint32_t)seg * 16,
             aG + (size_t)row * K_TOTAL + chunk * BK_ + seg * 8);
    }
#pragma unroll
    for (int i = 0; i < BN_ * S / THREADS; i++) {  // B: BN_ rows
        int idx = tid + i * THREADS;
        int row = idx / S, seg = idx % S;
        CP16(base + ASTG_ + (uint32_t)row * ROWB_ + (uint32_t)seg * 16,
             bG + (size_t)row * K_TOTAL + chunk * BK_ + seg * 8);
    }
}

template<int BN_, int BK_, int STAGES_>
__global__ void __launch_bounds__(THREADS, 1)
l4b_gemm_kernel(const void* __restrict__ xdt, void* __restrict__ out) {
    constexpr int BM = 128;
    constexpr int NCH = K_TOTAL / BK_;
    constexpr uint32_t ROWB_ = 2 * BK_ + 16;
    constexpr uint32_t ASTG_ = 128 * ROWB_;
    constexpr uint32_t STG_  = ASTG_ + BN_ * ROWB_;
    constexpr int NP = BN_ / 32;                   // n16-slabs per warp (WN=2)
    extern __shared__ char smem[];
    const uint32_t sb = smem_u32(smem);
    const int tid  = threadIdx.x;
    const int wid  = tid >> 5;
    const int lane = tid & 31;
    const int dt = detect_dtype((const uint32_t*)xdt);

    // rasterization: groups of 16 m-tiles for B-tile L2 reuse
    const int NT = N_TOTAL / BN_;
    const int GM = 16;
    int pid = blockIdx.x;
    int per_group = GM * NT;
    int grp = pid / per_group;
    int r = pid - grp * per_group;
    int m_tile = grp * GM + (r % GM);
    int n_tile = r / GM;

    const __half* aG = g_x + (size_t)m_tile * BM * K_TOTAL;
    const __half* bG = g_w + (size_t)n_tile * BN_ * K_TOTAL;

    const int warp_m = wid >> 1;   // 0..3 -> 32-row M slice
    const int warp_n = wid & 1;    // 0..1 -> BN_/2-col N slice

    float c[2][NP * 2][4] = {};

    // prologue: stages 0..STAGES-2
#pragma unroll
    for (int s = 0; s < STAGES_ - 1; s++) {
        load_chunk<BN_, BK_>(aG, bG, s, sb + (uint32_t)s * STG_);
        CP_COMMIT();
    }

    for (int i = 0; i < NCH; i++) {
        asm volatile("cp.async.wait_group %0;" :: "n"(STAGES_ - 2) : "memory");
        __syncthreads();

        uint32_t aBase = sb + (uint32_t)(i % STAGES_) * STG_;
        uint32_t bBase = aBase + ASTG_;
        const int arow = warp_m * 32 + (lane & 15);
        const int nrow0 = warp_n * (BN_ / 2) + (lane & 15);
        const uint32_t koff0 = (uint32_t)((lane >> 4) * 16);

#pragma unroll
        for (int ks = 0; ks < BK_ / 16; ks++) {
            const uint32_t koff = koff0 + (uint32_t)(ks * 32);
            uint32_t a[2][4];
            LDSM4(a[0][0], a[0][1], a[0][2], a[0][3],
                  aBase + (uint32_t)arow * ROWB_ + koff);
            LDSM4(a[1][0], a[1][1], a[1][2], a[1][3],
                  aBase + (uint32_t)(arow + 16) * ROWB_ + koff);

            // B-fragment software pipeline: prefetch slab np+1 before np's MMAs
            uint32_t bc0, bc1, bc2, bc3;           // r0=(n0-7,kLo) r1=(n8-15,kLo)
            LDSM4(bc0, bc1, bc2, bc3,              // r2=(n0-7,kHi) r3=(n8-15,kHi)
                  bBase + (uint32_t)nrow0 * ROWB_ + koff);
#pragma unroll
            for (int np = 0; np < NP; np++) {
                uint32_t bn0, bn1, bn2, bn3;
                if (np < NP - 1) {
                    LDSM4(bn0, bn1, bn2, bn3,
                          bBase + (uint32_t)(nrow0 + (np + 1) * 16) * ROWB_ + koff);
                }
                MMA16816(c[0][np * 2],     a[0], bc0, bc2);
                MMA16816(c[0][np * 2 + 1], a[0], bc1, bc3);
                MMA16816(c[1][np * 2],     a[1], bc0, bc2);
                MMA16816(c[1][np * 2 + 1], a[1], bc1, bc3);
                if (np < NP - 1) { bc0 = bn0; bc1 = bn1; bc2 = bn2; bc3 = bn3; }
            }
        }

        // issue next chunk's loads (R9 order: after MMA block); guarded, with
        // an unconditional commit (empty groups complete immediately, counting stays exact)
        int j = i + STAGES_ - 1;
        if (j < NCH)
            load_chunk<BN_, BK_>(aG, bG, j, sb + (uint32_t)(j % STAGES_) * STG_);
        CP_COMMIT();
    }

    // epilogue: fp16(acc) + bias in fp16 (matches reference), store per dtype
    {
        int m0 = m_tile * BM + warp_m * 32;
        int n0 = n_tile * BN_ + warp_n * (BN_ / 2);
        int mrow = lane >> 2;
        int ncol = (lane & 3) * 2;
#pragma unroll
        for (int mi = 0; mi < 2; mi++) {
            int m = m0 + mi * 16 + mrow;
            size_t orow0 = (size_t)m * N_TOTAL;
            size_t orow1 = (size_t)(m + 8) * N_TOTAL;
#pragma unroll
            for (int ni = 0; ni < NP * 2; ni++) {
                int n = n0 + ni * 8 + ncol;
                __half2 bb = *reinterpret_cast<const __half2*>(g_bias + n);
                __half2 v0 = __hadd2(__floats2half2_rn(c[mi][ni][0], c[mi][ni][1]), bb);
                __half2 v1 = __hadd2(__floats2half2_rn(c[mi][ni][2], c[mi][ni][3]), bb);
                if (dt == 2) {
                    *reinterpret_cast<float2*>((float*)out + orow0 + n) = __half22float2(v0);
                    *reinterpret_cast<float2*>((float*)out + orow1 + n) = __half22float2(v1);
                } else if (dt == 1) {
                    float2 f0 = __half22float2(v0), f1 = __half22float2(v1);
                    __nv_bfloat162 z0 = __floats2bfloat162_rn(f0.x, f0.y);
                    __nv_bfloat162 z1 = __floats2bfloat162_rn(f1.x, f1.y);
                    *reinterpret_cast<__nv_bfloat162*>((__nv_bfloat16*)out + orow0 + n) = z0;
                    *reinterpret_cast<__nv_bfloat162*>((__nv_bfloat16*)out + orow1 + n) = z1;
                } else {
                    *reinterpret_cast<__half2*>((__half*)out + orow0 + n) = v0;
                    *reinterpret_cast<__half2*>((__half*)out + orow1 + n) = v1;
                }
            }
        }
    }
}

// ===================== launch =====================
extern "C" void kernel_launch(void* const* d_in, const int* in_sizes, int n_in,
                              void* d_out, int out_size) {
    // identify inputs by unique element counts (order-scheme independent)
    const void* x = nullptr; const int* wq = nullptr;
    const void* wnorm = nullptr; const void* bias = nullptr;
    int x_idx = -1;
    for (int i = 0; i < n_in; i++) {
        if (in_sizes[i] == 67108864) { x = d_in[i]; x_idx = i; }
        else if (in_sizes[i] == 25165824) { wq = (const int*)d_in[i]; }
    }
    {
        const void* small[2] = {nullptr, nullptr};
        int ns = 0;
        for (int i = 0; i < n_in; i++)
            if (in_sizes[i] == 12288 && ns < 2) small[ns++] = d_in[i];
        if (x_idx == 0) { wnorm = small[0]; bias = small[1]; }   // dict order
        else           { bias  = small[0]; wnorm = small[1]; }   // alphabetical
    }

    fused_convert_kernel<<<XBLOCKS + WBLOCKS + BBLOCKS, THREADS>>>(x, wq, wnorm, bias);

    // main config: BN=256, BK=64, 3 stages -> 165888 B dynamic smem
    constexpr int MAIN_SMEM = 3 * (128 * 144 + 256 * 144);
    cudaError_t e = cudaFuncSetAttribute(l4b_gemm_kernel<256, 64, 3>,
                                         cudaFuncAttributeMaxDynamicSharedMemorySize,
                                         MAIN_SMEM);
    if (e == cudaSuccess) {
        l4b_gemm_kernel<256, 64, 3><<<(M_TOTAL / 128) * (N_TOTAL / 256), THREADS,
                                      MAIN_SMEM>>>(x, d_out);
    } else {
        // fallback: BN=128, BK=32, 2 stages -> 40960 B (< 48KB default limit)
        constexpr int FB_SMEM = 2 * (128 * 80 + 128 * 80);
        l4b_gemm_kernel<128, 32, 2><<<(M_TOTAL / 128) * (N_TOTAL / 128), THREADS,
                                      FB_SMEM>>>(x, d_out);
    }
}

// round 17
// speedup vs baseline: 1.0642x; 1.0066x over previous
#include <cuda_runtime.h>
#include <cuda_fp16.h>
#include <cuda_bf16.h>
#include <cstdint>

// ===================== problem constants =====================
#define M_TOTAL 16384
#define N_TOTAL 12288
#define K_TOTAL 4096
#define THREADS 256        // prep kernel block size
#define GTHREADS 512       // GEMM block size (16 warps, 4 per SMSP)

// fp16 staging buffers (device globals: allowed scratch)
static __device__ __align__(16) __half g_x[(size_t)M_TOTAL * K_TOTAL];     // 134 MB
static __device__ __align__(16) __half g_w[(size_t)N_TOTAL * K_TOTAL];     // 100 MB
static __device__ __align__(16) __half g_bias[N_TOTAL];

// ===================== PTX helpers (sm_80/90 baseline only) =====================
__device__ __forceinline__ uint32_t smem_u32(const void* p) {
    uint32_t a;
    asm("{ .reg .u64 t; cvta.to.shared.u64 t, %1; cvt.u32.u64 %0, t; }" : "=r"(a) : "l"(p));
    return a;
}
#define CP16(dst, src) asm volatile("cp.async.cg.shared.global [%0], [%1], 16;" :: "r"(dst), "l"(src) : "memory")
#define CP_COMMIT()    asm volatile("cp.async.commit_group;" ::: "memory")

#define LDSM4(r0, r1, r2, r3, addr) \
    asm volatile("ldmatrix.sync.aligned.m8n8.x4.shared.b16 {%0,%1,%2,%3}, [%4];" \
        : "=r"(r0), "=r"(r1), "=r"(r2), "=r"(r3) : "r"(addr))

#define MMA16816(c, a, b0, b1) \
    asm volatile("mma.sync.aligned.m16n8k16.row.col.f32.f16.f16.f32 " \
        "{%0,%1,%2,%3}, {%4,%5,%6,%7}, {%8,%9}, {%0,%1,%2,%3};" \
        : "+f"((c)[0]), "+f"((c)[1]), "+f"((c)[2]), "+f"((c)[3]) \
        : "r"((a)[0]), "r"((a)[1]), "r"((a)[2]), "r"((a)[3]), "r"(b0), "r"(b1))

__device__ __forceinline__ __half load_h(const void* p, int i, int dt) {
    if (dt == 2) return __float2half(((const float*)p)[i]);
    if (dt == 1) return __float2half(__bfloat162float(((const __nv_bfloat16*)p)[i]));
    return ((const __half*)p)[i];
}

// ===================== inline dtype detection (per block, no extra launch) ==========
// Words of x as fp32: plausible |v| => fp32 or bf16 (high half is a valid value);
// low 13 mantissa bits all zero => fp16-upcast-to-fp32 signature.
// Packed-fp16 words decode to tiny fp32 exponents and fail the magnitude test.
// All block threads must participate (uses __syncthreads_count); 256 sampled words.
__device__ __forceinline__ int detect_dtype(const uint32_t* __restrict__ xw) {
    int t = threadIdx.x;
    int condA = 0, condB = 0;
    if (t < 256) {
        uint32_t w = xw[t];
        float af = fabsf(__uint_as_float(w));
        condA = (af >= 9.5367431640625e-7f && af <= 16.0f);   // [2^-20, 2^4]
        condB = ((w & 0x1FFFu) == 0);
    }
    int a = __syncthreads_count(condA);
    int b = __syncthreads_count(condB);
    return (a > 128) ? ((b > 128) ? 2 : 1) : 0;
}

// ===================== launch 0: fused x-convert + weight-dequant + bias ============
#define XBLOCKS ((M_TOTAL * K_TOTAL / 8) / THREADS)          // 32768
#define WBLOCKS ((N_TOTAL * (K_TOTAL / 2) / 4) / THREADS)    // 24576
#define BBLOCKS (N_TOTAL / THREADS)                          // 48

__global__ void __launch_bounds__(THREADS)
fused_convert_kernel(const void* __restrict__ x, const int* __restrict__ q,
                     const void* __restrict__ norm, const void* __restrict__ bias) {
    int dt = detect_dtype((const uint32_t*)x);
    if (blockIdx.x < XBLOCKS) {
        // ---- x -> fp16 g_x, 8 elements per thread ----
        int i = blockIdx.x * THREADS + threadIdx.x;
        uint4 o;
        if (dt == 2) {
            const float4* p = (const float4*)x;
            float4 f0 = p[2 * i], f1 = p[2 * i + 1];
            __half2 h0 = __floats2half2_rn(f0.x, f0.y);
            __half2 h1 = __floats2half2_rn(f0.z, f0.w);
            __half2 h2 = __floats2half2_rn(f1.x, f1.y);
            __half2 h3 = __floats2half2_rn(f1.z, f1.w);
            o = make_uint4(*(uint32_t*)&h0, *(uint32_t*)&h1, *(uint32_t*)&h2, *(uint32_t*)&h3);
        } else if (dt == 1) {
            uint4 v = ((const uint4*)x)[i];
            uint32_t w[4] = {v.x, v.y, v.z, v.w}, r[4];
#pragma unroll
            for (int t = 0; t < 4; t++) {
                __nv_bfloat162 b2 = *reinterpret_cast<__nv_bfloat162*>(&w[t]);
                float2 f = __bfloat1622float2(b2);
                __half2 h = __floats2half2_rn(f.x, f.y);
                r[t] = *(uint32_t*)&h;
            }
            o = make_uint4(r[0], r[1], r[2], r[3]);
        } else {
            o = ((const uint4*)x)[i];
        }
        ((uint4*)g_x)[i] = o;
    } else if (blockIdx.x < XBLOCKS + WBLOCKS) {
        // ---- weight dequant: one int4 (4 packed bytes -> 8 fp16) per thread ----
        // w[2k] = fp16(lo)/fp16(15)*(fp16(2)*norm) - norm ; w[2k+1] with hi nibble.
        // Exact fp16-arithmetic emulation of the reference.
        int idx = (blockIdx.x - XBLOCKS) * THREADS + threadIdx.x;
        int4 v = reinterpret_cast<const int4*>(q)[idx];
        int row = idx >> 9;                            // 512 int4 per 2048-int32 row
        __half n  = load_h(norm, row, dt);
        __half n2 = __hmul(n, __float2half(2.0f));
        const __half f15 = __float2half(15.0f);
        int bv[4] = {v.x, v.y, v.z, v.w};
        uint32_t o[4];
#pragma unroll
        for (int t = 0; t < 4; t++) {
            int b = bv[t];
            __half lo = __float2half((float)(b & 15));
            __half hi = __float2half((float)((b >> 4) & 15));
            __half wl = __hsub(__hmul(__hdiv(lo, f15), n2), n);
            __half wh = __hsub(__hmul(__hdiv(hi, f15), n2), n);
            __half2 h2 = __halves2half2(wl, wh);
            o[t] = *reinterpret_cast<uint32_t*>(&h2);
        }
        reinterpret_cast<uint4*>(g_w)[idx] = make_uint4(o[0], o[1], o[2], o[3]);
    } else {
        // ---- bias -> fp16 ----
        int i = (blockIdx.x - XBLOCKS - WBLOCKS) * THREADS + threadIdx.x;
        g_bias[i] = load_h(bias, i, dt);
    }
}

// ===================== launch 1: GEMM =====================
// D[m][n] = sum_k g_x[m][k] * g_w[n][k] + bias[n]
// CTA 128x256, 16 warps (4M x 4N), warp tile 32x64, m16n8k16 HMMA,
// 3-stage cp.async. 512 threads -> 4 warps/SMSP for latency hiding.
template<int BN_, int BK_>
__device__ __forceinline__ void load_chunk(const __half* __restrict__ aG,
                                           const __half* __restrict__ bG,
                                           int chunk, uint32_t base) {
    constexpr uint32_t ROWB_ = 2 * BK_ + 16;
    constexpr int S = BK_ / 8;                     // 16B segs per row
    constexpr uint32_t ASTG_ = 128 * ROWB_;
    int tid = threadIdx.x;
#pragma unroll
    for (int i = 0; i < 128 * S / GTHREADS; i++) { // A: 128 rows
        int idx = tid + i * GTHREADS;
        int row = idx / S, seg = idx % S;
        CP16(base + (uint32_t)row * ROWB_ + (uint32_t)seg * 16,
             aG + (size_t)row * K_TOTAL + chunk * BK_ + seg * 8);
    }
#pragma unroll
    for (int i = 0; i < BN_ * S / GTHREADS; i++) { // B: BN_ rows
        int idx = tid + i * GTHREADS;
        int row = idx / S, seg = idx % S;
        CP16(base + ASTG_ + (uint32_t)row * ROWB_ + (uint32_t)seg * 16,
             bG + (size_t)row * K_TOTAL + chunk * BK_ + seg * 8);
    }
}

template<int BN_, int BK_, int STAGES_>
__global__ void __launch_bounds__(GTHREADS, 1)
l4b_gemm_kernel(const void* __restrict__ xdt, void* __restrict__ out) {
    constexpr int BM = 128;
    constexpr int NCH = K_TOTAL / BK_;
    constexpr uint32_t ROWB_ = 2 * BK_ + 16;
    constexpr uint32_t ASTG_ = 128 * ROWB_;
    constexpr uint32_t STG_  = ASTG_ + BN_ * ROWB_;
    constexpr int NP = BN_ / 64;                   // n16-slabs per warp (WN=4)
    extern __shared__ char smem[];
    const uint32_t sb = smem_u32(smem);
    const int tid  = threadIdx.x;
    const int wid  = tid >> 5;
    const int lane = tid & 31;
    const int dt = detect_dtype((const uint32_t*)xdt);

    // rasterization: groups of 16 m-tiles for B-tile L2 reuse
    const int NT = N_TOTAL / BN_;
    const int GM = 16;
    int pid = blockIdx.x;
    int per_group = GM * NT;
    int grp = pid / per_group;
    int r = pid - grp * per_group;
    int m_tile = grp * GM + (r % GM);
    int n_tile = r / GM;

    const __half* aG = g_x + (size_t)m_tile * BM * K_TOTAL;
    const __half* bG = g_w + (size_t)n_tile * BN_ * K_TOTAL;

    const int warp_m = wid >> 2;   // 0..3 -> 32-row M slice
    const int warp_n = wid & 3;    // 0..3 -> BN_/4-col N slice

    float c[2][NP * 2][4] = {};

    // prologue: stages 0..STAGES-2
#pragma unroll
    for (int s = 0; s < STAGES_ - 1; s++) {
        load_chunk<BN_, BK_>(aG, bG, s, sb + (uint32_t)s * STG_);
        CP_COMMIT();
    }

    for (int i = 0; i < NCH; i++) {
        asm volatile("cp.async.wait_group %0;" :: "n"(STAGES_ - 2) : "memory");
        __syncthreads();

        uint32_t aBase = sb + (uint32_t)(i % STAGES_) * STG_;
        uint32_t bBase = aBase + ASTG_;
        const int arow = warp_m * 32 + (lane & 15);
        const int nrow0 = warp_n * (BN_ / 4) + (lane & 15);
        const uint32_t koff0 = (uint32_t)((lane >> 4) * 16);

#pragma unroll
        for (int ks = 0; ks < BK_ / 16; ks++) {
            const uint32_t koff = koff0 + (uint32_t)(ks * 32);
            uint32_t a[2][4];
            LDSM4(a[0][0], a[0][1], a[0][2], a[0][3],
                  aBase + (uint32_t)arow * ROWB_ + koff);
            LDSM4(a[1][0], a[1][1], a[1][2], a[1][3],
                  aBase + (uint32_t)(arow + 16) * ROWB_ + koff);

            // B-fragment software pipeline: prefetch slab np+1 before np's MMAs
            uint32_t bc0, bc1, bc2, bc3;           // r0=(n0-7,kLo) r1=(n8-15,kLo)
            LDSM4(bc0, bc1, bc2, bc3,              // r2=(n0-7,kHi) r3=(n8-15,kHi)
                  bBase + (uint32_t)nrow0 * ROWB_ + koff);
#pragma unroll
            for (int np = 0; np < NP; np++) {
                uint32_t bn0, bn1, bn2, bn3;
                if (np < NP - 1) {
                    LDSM4(bn0, bn1, bn2, bn3,
                          bBase + (uint32_t)(nrow0 + (np + 1) * 16) * ROWB_ + koff);
                }
                MMA16816(c[0][np * 2],     a[0], bc0, bc2);
                MMA16816(c[0][np * 2 + 1], a[0], bc1, bc3);
                MMA16816(c[1][np * 2],     a[1], bc0, bc2);
                MMA16816(c[1][np * 2 + 1], a[1], bc1, bc3);
                if (np < NP - 1) { bc0 = bn0; bc1 = bn1; bc2 = bn2; bc3 = bn3; }
            }
        }

        // issue next chunk's loads; guarded, with unconditional commit
        // (empty groups complete immediately, counting stays exact)
        int j = i + STAGES_ - 1;
        if (j < NCH)
            load_chunk<BN_, BK_>(aG, bG, j, sb + (uint32_t)(j % STAGES_) * STG_);
        CP_COMMIT();
    }

    // epilogue: fp16(acc) + bias in fp16 (matches reference), store per dtype
    {
        int m0 = m_tile * BM + warp_m * 32;
        int n0 = n_tile * BN_ + warp_n * (BN_ / 4);
        int mrow = lane >> 2;
        int ncol = (lane & 3) * 2;
#pragma unroll
        for (int mi = 0; mi < 2; mi++) {
            int m = m0 + mi * 16 + mrow;
            size_t orow0 = (size_t)m * N_TOTAL;
            size_t orow1 = (size_t)(m + 8) * N_TOTAL;
#pragma unroll
            for (int ni = 0; ni < NP * 2; ni++) {
                int n = n0 + ni * 8 + ncol;
                __half2 bb = *reinterpret_cast<const __half2*>(g_bias + n);
                __half2 v0 = __hadd2(__floats2half2_rn(c[mi][ni][0], c[mi][ni][1]), bb);
                __half2 v1 = __hadd2(__floats2half2_rn(c[mi][ni][2], c[mi][ni][3]), bb);
                if (dt == 2) {
                    *reinterpret_cast<float2*>((float*)out + orow0 + n) = __half22float2(v0);
                    *reinterpret_cast<float2*>((float*)out + orow1 + n) = __half22float2(v1);
                } else if (dt == 1) {
                    float2 f0 = __half22float2(v0), f1 = __half22float2(v1);
                    __nv_bfloat162 z0 = __floats2bfloat162_rn(f0.x, f0.y);
                    __nv_bfloat162 z1 = __floats2bfloat162_rn(f1.x, f1.y);
                    *reinterpret_cast<__nv_bfloat162*>((__nv_bfloat16*)out + orow0 + n) = z0;
                    *reinterpret_cast<__nv_bfloat162*>((__nv_bfloat16*)out + orow1 + n) = z1;
                } else {
                    *reinterpret_cast<__half2*>((__half*)out + orow0 + n) = v0;
                    *reinterpret_cast<__half2*>((__half*)out + orow1 + n) = v1;
                }
            }
        }
    }
}

// ===================== launch =====================
extern "C" void kernel_launch(void* const* d_in, const int* in_sizes, int n_in,
                              void* d_out, int out_size) {
    // identify inputs by unique element counts (order-scheme independent)
    const void* x = nullptr; const int* wq = nullptr;
    const void* wnorm = nullptr; const void* bias = nullptr;
    int x_idx = -1;
    for (int i = 0; i < n_in; i++) {
        if (in_sizes[i] == 67108864) { x = d_in[i]; x_idx = i; }
        else if (in_sizes[i] == 25165824) { wq = (const int*)d_in[i]; }
    }
    {
        const void* small[2] = {nullptr, nullptr};
        int ns = 0;
        for (int i = 0; i < n_in; i++)
            if (in_sizes[i] == 12288 && ns < 2) small[ns++] = d_in[i];
        if (x_idx == 0) { wnorm = small[0]; bias = small[1]; }   // dict order
        else           { bias  = small[0]; wnorm = small[1]; }   // alphabetical
    }

    fused_convert_kernel<<<XBLOCKS + WBLOCKS + BBLOCKS, THREADS>>>(x, wq, wnorm, bias);

    // main config: BN=256, BK=64, 3 stages -> 165888 B dynamic smem
    constexpr int MAIN_SMEM = 3 * (128 * 144 + 256 * 144);
    cudaError_t e = cudaFuncSetAttribute(l4b_gemm_kernel<256, 64, 3>,
                                         cudaFuncAttributeMaxDynamicSharedMemorySize,
                                         MAIN_SMEM);
    if (e == cudaSuccess) {
        l4b_gemm_kernel<256, 64, 3><<<(M_TOTAL / 128) * (N_TOTAL / 256), GTHREADS,
                                      MAIN_SMEM>>>(x, d_out);
    } else {
        // fallback: BN=128, BK=32, 2 stages -> 40960 B (< 48KB default limit)
        constexpr int FB_SMEM = 2 * (128 * 80 + 128 * 80);
        l4b_gemm_kernel<128, 32, 2><<<(M_TOTAL / 128) * (N_TOTAL / 128), GTHREADS,
                                      FB_SMEM>>>(x, d_out);
    }
}